// round 2
// baseline (speedup 1.0000x reference)
#include <cuda_runtime.h>
#include <math.h>

#define BB    32
#define TT    1024
#define CCH   512
#define CONDC 256
#define LLEN  252
#define SSEQ  128
#define MTOT  (BB*TT)

// Scratch (static device globals: allocation-free per harness rules)
__device__ float g_query[(size_t)MTOT * CCH];        // 64 MB
__device__ float g_h[(size_t)MTOT * 2 * CCH];        // 128 MB
__device__ float g_Pk[BB * CCH];
__device__ float g_Pv[BB * CCH];
__device__ float g_WkSum[CCH];
__device__ float g_WvSum[CCH];

struct Params {
    const float *x, *cond_emb, *Wq, *bq, *Wk, *bk, *Wv, *bv,
                *conv_w, *conv_b, *ln1_w, *ln1_b, *W1, *b1, *W2, *b2,
                *ln2_w, *ln2_b;
};

__device__ __forceinline__ float wsum(float v) {
    #pragma unroll
    for (int o = 16; o; o >>= 1) v += __shfl_xor_sync(0xffffffffu, v, o);
    return v;
}
__device__ __forceinline__ float wmax(float v) {
    #pragma unroll
    for (int o = 16; o; o >>= 1) v = fmaxf(v, __shfl_xor_sync(0xffffffffu, v, o));
    return v;
}

// ---------------------------------------------------------------------------
// Precompute: Pk[b,c] = pad[b]·Wk[c,:], Pv likewise; plus row-sums of Wk/Wv.
// grid (BB+1, 2): y=0 -> K, y=1 -> V; x==BB computes the row sums.
// ---------------------------------------------------------------------------
__global__ void k_precompute(Params p) {
    __shared__ float padS[CONDC];
    const int bb = blockIdx.x;
    const int which = blockIdx.y;
    const float* W = which ? p.Wv : p.Wk;

    if (bb == BB) {
        for (int c = threadIdx.x; c < CCH; c += blockDim.x) {
            float s = 0.f;
            const float* wr = W + (size_t)c * CONDC;
            #pragma unroll 4
            for (int j = 0; j < CONDC; ++j) s += wr[j];
            (which ? g_WvSum : g_WkSum)[c] = s;
        }
        return;
    }
    // circular pad by 2: pad[j] = cond_emb[b, (j-2) mod L]
    for (int j = threadIdx.x; j < CONDC; j += blockDim.x) {
        int src = (j + LLEN - 2) % LLEN;
        padS[j] = p.cond_emb[bb * LLEN + src];
    }
    __syncthreads();
    for (int c = threadIdx.x; c < CCH; c += blockDim.x) {
        float s = 0.f;
        const float* wr = W + (size_t)c * CONDC;
        #pragma unroll 4
        for (int j = 0; j < CONDC; ++j) s = fmaf(padS[j], wr[j], s);
        (which ? g_Pv : g_Pk)[bb * CCH + c] = s;
    }
}

// ---------------------------------------------------------------------------
// Tiled GEMM body: 32 rows x 512 cols per block, 256 threads.
// warp = row group (4 rows), lane owns cols c = lane + 32*j (j<16).
// wS[kk][c]: bank = c%32 = lane -> conflict-free compute reads.
// ---------------------------------------------------------------------------
template<int KDIM>
__device__ __forceinline__ void gemm_body(
    const float* __restrict__ inp, const float* __restrict__ wgt,
    int m0, int nbase, float (&acc)[4][16],
    float (&xS)[32][16], float (&wS)[16][512])
{
    const int tid  = threadIdx.x;
    const int lane = tid & 31;
    const int warp = tid >> 5;
    const int r4   = tid >> 2;          // 0..63
    const int kq   = (tid & 3) << 2;    // 0,4,8,12

    #pragma unroll 1
    for (int k0 = 0; k0 < KDIM; k0 += 16) {
        if (tid < 128) {
            float4 v = *(const float4*)(inp + (size_t)(m0 + r4) * KDIM + k0 + kq);
            *(float4*)&xS[r4][kq] = v;
        }
        #pragma unroll
        for (int it = 0; it < 8; ++it) {
            int c = it * 64 + r4;
            float4 v = *(const float4*)(wgt + (size_t)(nbase + c) * KDIM + k0 + kq);
            wS[kq + 0][c] = v.x; wS[kq + 1][c] = v.y;
            wS[kq + 2][c] = v.z; wS[kq + 3][c] = v.w;
        }
        __syncthreads();
        #pragma unroll
        for (int kk = 0; kk < 16; ++kk) {
            const float a0 = xS[warp * 4 + 0][kk];
            const float a1 = xS[warp * 4 + 1][kk];
            const float a2 = xS[warp * 4 + 2][kk];
            const float a3 = xS[warp * 4 + 3][kk];
            #pragma unroll
            for (int j = 0; j < 16; ++j) {
                const float w = wS[kk][lane + 32 * j];
                acc[0][j] = fmaf(a0, w, acc[0][j]);
                acc[1][j] = fmaf(a1, w, acc[1][j]);
                acc[2][j] = fmaf(a2, w, acc[2][j]);
                acc[3][j] = fmaf(a3, w, acc[3][j]);
            }
        }
        __syncthreads();
    }
}

// ---------------------------------------------------------------------------
// Kernel B: q = x@Wq.T + bq, rank-1-collapsed attention, +LN1 -> g_query
// ---------------------------------------------------------------------------
__global__ __launch_bounds__(256) void k_qattn(Params p) {
    __shared__ float xS[32][16];
    __shared__ float wS[16][512];
    __shared__ float convW[SSEQ], convB[SSEQ];

    const int tid = threadIdx.x;
    if (tid < SSEQ) { convW[tid] = p.conv_w[tid]; convB[tid] = p.conv_b[tid]; }

    const int m0 = blockIdx.x * 32;
    float acc[4][16];
    #pragma unroll
    for (int i = 0; i < 4; ++i)
        #pragma unroll
        for (int j = 0; j < 16; ++j) acc[i][j] = 0.f;

    gemm_body<CCH>(p.x, p.Wq, m0, 0, acc, xS, wS);

    const int lane = tid & 31, warp = tid >> 5;
    const int b = m0 / TT;

    // q = acc + bq; attention scalars u = q·Pk[b], v = q·ΣWk, c0 = q·bk
    float u[4] = {0,0,0,0}, vv[4] = {0,0,0,0}, c0[4] = {0,0,0,0};
    #pragma unroll
    for (int j = 0; j < 16; ++j) {
        const int c = lane + 32 * j;
        const float bqc = p.bq[c];
        const float pkc = g_Pk[b * CCH + c];
        const float wks = g_WkSum[c];
        const float bkc = p.bk[c];
        #pragma unroll
        for (int i = 0; i < 4; ++i) {
            const float q = acc[i][j] + bqc;
            acc[i][j] = q;
            u[i]  = fmaf(q, pkc, u[i]);
            vv[i] = fmaf(q, wks, vv[i]);
            c0[i] = fmaf(q, bkc, c0[i]);
        }
    }
    const float scl = rsqrtf((float)CCH);
    float w1[4], w2[4];
    #pragma unroll
    for (int i = 0; i < 4; ++i) {
        u[i] = wsum(u[i]); vv[i] = wsum(vv[i]); c0[i] = wsum(c0[i]);
        float sc[4], mx = -3.4e38f;
        #pragma unroll
        for (int ss = 0; ss < 4; ++ss) {
            const int s = lane + 32 * ss;
            sc[ss] = scl * (convW[s] * u[i] + convB[s] * vv[i] + c0[i]);
            mx = fmaxf(mx, sc[ss]);
        }
        mx = wmax(mx);
        float z = 0.f, a1 = 0.f, a2 = 0.f;
        #pragma unroll
        for (int ss = 0; ss < 4; ++ss) {
            const int s = lane + 32 * ss;
            const float e = expf(sc[ss] - mx);
            z += e; a1 = fmaf(e, convW[s], a1); a2 = fmaf(e, convB[s], a2);
        }
        z = wsum(z); a1 = wsum(a1); a2 = wsum(a2);
        w1[i] = a1 / z; w2[i] = a2 / z;
    }
    // y = q + attn_out; LN1 stats
    float su[4] = {0,0,0,0}, sq[4] = {0,0,0,0};
    #pragma unroll
    for (int j = 0; j < 16; ++j) {
        const int c = lane + 32 * j;
        const float pvc = g_Pv[b * CCH + c];
        const float wvs = g_WvSum[c];
        const float bvc = p.bv[c];
        #pragma unroll
        for (int i = 0; i < 4; ++i) {
            const float y = acc[i][j] + fmaf(w1[i], pvc, fmaf(w2[i], wvs, bvc));
            acc[i][j] = y;
            su[i] += y;
            sq[i] = fmaf(y, y, sq[i]);
        }
    }
    float mu[4], rs[4];
    #pragma unroll
    for (int i = 0; i < 4; ++i) {
        const float s1 = wsum(su[i]);
        const float s2 = wsum(sq[i]);
        mu[i] = s1 * (1.f / CCH);
        const float var = s2 * (1.f / CCH) - mu[i] * mu[i];
        rs[i] = rsqrtf(var + 1e-5f);
    }
    #pragma unroll
    for (int j = 0; j < 16; ++j) {
        const int c = lane + 32 * j;
        const float lw = p.ln1_w[c], lb = p.ln1_b[c];
        #pragma unroll
        for (int i = 0; i < 4; ++i) {
            g_query[(size_t)(m0 + warp * 4 + i) * CCH + c] =
                (acc[i][j] - mu[i]) * rs[i] * lw + lb;
        }
    }
}

// ---------------------------------------------------------------------------
// Kernel C1: h = gelu(query@W1.T + b1), exact erf gelu. grid.y picks N-half.
// ---------------------------------------------------------------------------
__global__ __launch_bounds__(256) void k_ffn1(Params p) {
    __shared__ float xS[32][16];
    __shared__ float wS[16][512];
    const int m0 = blockIdx.x * 32;
    const int no = blockIdx.y * 512;
    float acc[4][16];
    #pragma unroll
    for (int i = 0; i < 4; ++i)
        #pragma unroll
        for (int j = 0; j < 16; ++j) acc[i][j] = 0.f;

    gemm_body<CCH>(g_query, p.W1, m0, no, acc, xS, wS);

    const int lane = threadIdx.x & 31, warp = threadIdx.x >> 5;
    #pragma unroll
    for (int j = 0; j < 16; ++j) {
        const int c = lane + 32 * j;
        const float bc = p.b1[no + c];
        #pragma unroll
        for (int i = 0; i < 4; ++i) {
            const float v = acc[i][j] + bc;
            const float g = 0.5f * v * (1.0f + erff(v * 0.70710678118654752f));
            g_h[(size_t)(m0 + warp * 4 + i) * (2 * CCH) + no + c] = g;
        }
    }
}

// ---------------------------------------------------------------------------
// Kernel C2: out = LN2(query + h@W2.T + b2) + x
// ---------------------------------------------------------------------------
__global__ __launch_bounds__(256) void k_ffn2(Params p, float* __restrict__ out) {
    __shared__ float xS[32][16];
    __shared__ float wS[16][512];
    const int m0 = blockIdx.x * 32;
    float acc[4][16];
    #pragma unroll
    for (int i = 0; i < 4; ++i)
        #pragma unroll
        for (int j = 0; j < 16; ++j) acc[i][j] = 0.f;

    gemm_body<2 * CCH>(g_h, p.W2, m0, 0, acc, xS, wS);

    const int lane = threadIdx.x & 31, warp = threadIdx.x >> 5;
    float su[4] = {0,0,0,0}, sq[4] = {0,0,0,0};
    #pragma unroll
    for (int j = 0; j < 16; ++j) {
        const int c = lane + 32 * j;
        const float b2c = p.b2[c];
        #pragma unroll
        for (int i = 0; i < 4; ++i) {
            const size_t idx = (size_t)(m0 + warp * 4 + i) * CCH + c;
            const float y = acc[i][j] + b2c + g_query[idx];
            acc[i][j] = y;
            su[i] += y;
            sq[i] = fmaf(y, y, sq[i]);
        }
    }
    float mu[4], rs[4];
    #pragma unroll
    for (int i = 0; i < 4; ++i) {
        const float s1 = wsum(su[i]);
        const float s2 = wsum(sq[i]);
        mu[i] = s1 * (1.f / CCH);
        const float var = s2 * (1.f / CCH) - mu[i] * mu[i];
        rs[i] = rsqrtf(var + 1e-5f);
    }
    #pragma unroll
    for (int j = 0; j < 16; ++j) {
        const int c = lane + 32 * j;
        const float lw = p.ln2_w[c], lb = p.ln2_b[c];
        #pragma unroll
        for (int i = 0; i < 4; ++i) {
            const size_t idx = (size_t)(m0 + warp * 4 + i) * CCH + c;
            out[idx] = (acc[i][j] - mu[i]) * rs[i] * lw + lb + p.x[idx];
        }
    }
}

// ---------------------------------------------------------------------------
extern "C" void kernel_launch(void* const* d_in, const int* in_sizes, int n_in,
                              void* d_out, int out_size) {
    Params p;
    p.x        = (const float*)d_in[0];
    p.cond_emb = (const float*)d_in[1];
    p.Wq       = (const float*)d_in[2];
    p.bq       = (const float*)d_in[3];
    p.Wk       = (const float*)d_in[4];
    p.bk       = (const float*)d_in[5];
    p.Wv       = (const float*)d_in[6];
    p.bv       = (const float*)d_in[7];
    p.conv_w   = (const float*)d_in[8];
    p.conv_b   = (const float*)d_in[9];
    p.ln1_w    = (const float*)d_in[10];
    p.ln1_b    = (const float*)d_in[11];
    p.W1       = (const float*)d_in[12];
    p.b1       = (const float*)d_in[13];
    p.W2       = (const float*)d_in[14];
    p.b2       = (const float*)d_in[15];
    p.ln2_w    = (const float*)d_in[16];
    p.ln2_b    = (const float*)d_in[17];
    float* out = (float*)d_out;

    k_precompute<<<dim3(BB + 1, 2), 256>>>(p);
    k_qattn<<<MTOT / 32, 256>>>(p);
    k_ffn1<<<dim3(MTOT / 32, 2), 256>>>(p);
    k_ffn2<<<MTOT / 32, 256>>>(p, out);
}

// round 5
// speedup vs baseline: 3.9376x; 3.9376x over previous
#include <cuda_runtime.h>
#include <math.h>
#include <stdint.h>

#define BB    32
#define TT    1024
#define CCH   512
#define CONDC 256
#define LLEN  252
#define SSEQ  128
#define MTOT  (BB*TT)

// GEMM tiling: block = 32 rows x 512 cols, 8 warps, warp tile 32x64 (m16n8k8 tf32)
#define BK        32
#define A_STAGE   1024          // 32*32 floats
#define B_STAGE   16384         // 512*32 floats
#define SMEM_FLT  (2*A_STAGE + 2*B_STAGE)
#define SMEM_BYTES (SMEM_FLT*4)

// Scratch (static device globals: allocation-free per harness rules)
__device__ float g_query[(size_t)MTOT * CCH];        // 64 MB
__device__ float g_h[(size_t)MTOT * 2 * CCH];        // 128 MB
__device__ float g_Pk[BB * CCH];
__device__ float g_Pv[BB * CCH];
__device__ float g_WkSum[CCH];
__device__ float g_WvSum[CCH];

struct Params {
    const float *x, *cond_emb, *Wq, *bq, *Wk, *bk, *Wv, *bv,
                *conv_w, *conv_b, *ln1_w, *ln1_b, *W1, *b1, *W2, *b2,
                *ln2_w, *ln2_b;
};

// ---------------------------------------------------------------------------
// primitives
// ---------------------------------------------------------------------------
__device__ __forceinline__ void mma8(float* c, uint32_t a0, uint32_t a1,
                                     uint32_t a2, uint32_t a3,
                                     uint32_t b0, uint32_t b1) {
    asm volatile(
        "mma.sync.aligned.m16n8k8.row.col.f32.tf32.tf32.f32 "
        "{%0,%1,%2,%3}, {%4,%5,%6,%7}, {%8,%9}, {%0,%1,%2,%3};\n"
        : "+f"(c[0]), "+f"(c[1]), "+f"(c[2]), "+f"(c[3])
        : "r"(a0), "r"(a1), "r"(a2), "r"(a3), "r"(b0), "r"(b1));
}

__device__ __forceinline__ void cpa(float* dst, const float* src) {
    unsigned d = (unsigned)__cvta_generic_to_shared(dst);
    asm volatile("cp.async.cg.shared.global [%0], [%1], 16;\n" :: "r"(d), "l"(src));
}
#define CP_COMMIT() asm volatile("cp.async.commit_group;\n")
template<int N> __device__ __forceinline__ void waitg() {
    asm volatile("cp.async.wait_group %0;\n" :: "n"(N));
}

__device__ __forceinline__ float qred(float v) {   // reduce over tig quad (lanes 4g..4g+3)
    v += __shfl_xor_sync(0xffffffffu, v, 1);
    v += __shfl_xor_sync(0xffffffffu, v, 2);
    return v;
}

// ---------------------------------------------------------------------------
// stage one k-tile (32 wide) into smem with XOR swizzle phys(kk)=kk^(4*(r&7))
// ---------------------------------------------------------------------------
__device__ __forceinline__ void load_tile(float* As, float* Bs,
                                          const float* __restrict__ inp,
                                          const float* __restrict__ wgt,
                                          int m0, int nbase, int K, int k0, int tid) {
    const int u = tid & 7, r = tid >> 3;   // r: 0..31, u: float4 index
    cpa(As + r * BK + 4 * (u ^ (r & 7)), inp + (size_t)(m0 + r) * K + k0 + 4 * u);
    #pragma unroll
    for (int it = 0; it < 16; ++it) {
        const int c = it * 32 + r;
        cpa(Bs + c * BK + 4 * (u ^ (c & 7)), wgt + (size_t)(nbase + c) * K + k0 + 4 * u);
    }
}

// ---------------------------------------------------------------------------
// Tensor-core GEMM: acc[2][8][4] += inp[m0:m0+32, :K] @ wgt[nbase:nbase+512, :K]^T
// ---------------------------------------------------------------------------
template<int KDIM>
__device__ __forceinline__ void gemm_mma(const float* __restrict__ inp,
                                         const float* __restrict__ wgt,
                                         int m0, int nbase,
                                         float acc[2][8][4], float* sm) {
    float* A0 = sm;
    float* B0 = sm + 2 * A_STAGE;
    const int NT  = KDIM / BK;
    const int tid = threadIdx.x;
    const int lane = tid & 31, w = tid >> 5;
    const int gid = lane >> 2, tig = lane & 3;
    const int xs = 4 * gid;

    load_tile(A0, B0, inp, wgt, m0, nbase, KDIM, 0, tid); CP_COMMIT();
    load_tile(A0 + A_STAGE, B0 + B_STAGE, inp, wgt, m0, nbase, KDIM, BK, tid); CP_COMMIT();

    #pragma unroll 1
    for (int t = 0; t < NT; ++t) {
        if (t + 1 < NT) waitg<1>(); else waitg<0>();
        __syncthreads();
        const float* Ast = A0 + (t & 1) * A_STAGE;
        const float* Bst = B0 + (t & 1) * B_STAGE;

        #pragma unroll
        for (int ks = 0; ks < 4; ++ks) {
            const int kk0 = ks * 8;
            uint32_t b0[8], b1[8];
            #pragma unroll
            for (int j = 0; j < 8; ++j) {
                const float* bp = Bst + (w * 64 + j * 8 + gid) * BK;
                b0[j] = __float_as_uint(bp[(kk0 + tig)     ^ xs]);
                b1[j] = __float_as_uint(bp[(kk0 + tig + 4) ^ xs]);
            }
            #pragma unroll
            for (int mt = 0; mt < 2; ++mt) {
                const float* apl = Ast + (mt * 16 + gid) * BK;
                const float* aph = apl + 8 * BK;
                uint32_t a0 = __float_as_uint(apl[(kk0 + tig)     ^ xs]);
                uint32_t a1 = __float_as_uint(aph[(kk0 + tig)     ^ xs]);
                uint32_t a2 = __float_as_uint(apl[(kk0 + tig + 4) ^ xs]);
                uint32_t a3 = __float_as_uint(aph[(kk0 + tig + 4) ^ xs]);
                #pragma unroll
                for (int j = 0; j < 8; ++j)
                    mma8(acc[mt][j], a0, a1, a2, a3, b0[j], b1[j]);
            }
        }
        __syncthreads();
        if (t + 2 < NT) {
            load_tile(A0 + (t & 1) * A_STAGE, B0 + (t & 1) * B_STAGE,
                      inp, wgt, m0, nbase, KDIM, (t + 2) * BK, tid);
            CP_COMMIT();
        }
    }
}

// ---------------------------------------------------------------------------
// Precompute: Pk[b,c] = pad[b]·Wk[c,:], Pv likewise; plus weight row-sums
// ---------------------------------------------------------------------------
__global__ void k_precompute(Params p) {
    __shared__ float padS[CONDC];
    const int bb = blockIdx.x;
    const int which = blockIdx.y;
    const float* W = which ? p.Wv : p.Wk;

    if (bb == BB) {
        for (int c = threadIdx.x; c < CCH; c += blockDim.x) {
            float s = 0.f;
            const float* wr = W + (size_t)c * CONDC;
            #pragma unroll 4
            for (int j = 0; j < CONDC; ++j) s += wr[j];
            (which ? g_WvSum : g_WkSum)[c] = s;
        }
        return;
    }
    for (int j = threadIdx.x; j < CONDC; j += blockDim.x) {
        int src = (j + LLEN - 2) % LLEN;
        padS[j] = p.cond_emb[bb * LLEN + src];
    }
    __syncthreads();
    for (int c = threadIdx.x; c < CCH; c += blockDim.x) {
        float s = 0.f;
        const float* wr = W + (size_t)c * CONDC;
        #pragma unroll 4
        for (int j = 0; j < CONDC; ++j) s = fmaf(padS[j], wr[j], s);
        (which ? g_Pv : g_Pk)[bb * CCH + c] = s;
    }
}

// ---------------------------------------------------------------------------
// Kernel B: q = x@Wq.T + bq -> rank-1 attention -> +LN1 -> g_query
// ---------------------------------------------------------------------------
__global__ __launch_bounds__(256, 1) void k_qattn(Params p) {
    extern __shared__ float sm[];
    __shared__ float convW[SSEQ], convB[SSEQ];

    const int tid = threadIdx.x;
    if (tid < SSEQ) { convW[tid] = p.conv_w[tid]; convB[tid] = p.conv_b[tid]; }

    const int m0 = blockIdx.x * 32;
    float acc[2][8][4];
    #pragma unroll
    for (int mt = 0; mt < 2; ++mt)
        #pragma unroll
        for (int j = 0; j < 8; ++j)
            #pragma unroll
            for (int e = 0; e < 4; ++e) acc[mt][j][e] = 0.f;

    gemm_mma<CCH>(p.x, p.Wq, m0, 0, acc, sm);

    const int lane = tid & 31, w = tid >> 5;
    const int gid = lane >> 2, tig = lane & 3;
    const int b = m0 / TT;
    const float* Pkb = g_Pk + b * CCH;
    const float* Pvb = g_Pv + b * CCH;

    // ---- attention scalars: u = q·Pk, v = q·ΣWk, c0 = q·bk (per row) ----
    float pu[2][2] = {{0,0},{0,0}}, pv[2][2] = {{0,0},{0,0}}, pc[2][2] = {{0,0},{0,0}};
    #pragma unroll
    for (int mt = 0; mt < 2; ++mt)
        #pragma unroll
        for (int j = 0; j < 8; ++j)
            #pragma unroll
            for (int e = 0; e < 2; ++e) {
                const int c = w * 64 + j * 8 + 2 * tig + e;
                const float bqc = p.bq[c], pkc = Pkb[c], wks = g_WkSum[c], bkc = p.bk[c];
                const float q0 = acc[mt][j][e]     + bqc;
                const float q1 = acc[mt][j][2 + e] + bqc;
                acc[mt][j][e] = q0; acc[mt][j][2 + e] = q1;
                pu[mt][0] = fmaf(q0, pkc, pu[mt][0]); pu[mt][1] = fmaf(q1, pkc, pu[mt][1]);
                pv[mt][0] = fmaf(q0, wks, pv[mt][0]); pv[mt][1] = fmaf(q1, wks, pv[mt][1]);
                pc[mt][0] = fmaf(q0, bkc, pc[mt][0]); pc[mt][1] = fmaf(q1, bkc, pc[mt][1]);
            }
    float* red = sm;                // [3][32][9]
    float* w1s = sm + 864;
    float* w2s = sm + 896;
    float* mus = sm + 928;
    float* rss = sm + 960;
    #pragma unroll
    for (int mt = 0; mt < 2; ++mt)
        #pragma unroll
        for (int h = 0; h < 2; ++h) {
            const float ru = qred(pu[mt][h]), rv = qred(pv[mt][h]), rc = qred(pc[mt][h]);
            if (tig == 0) {
                const int row = mt * 16 + h * 8 + gid;
                red[row * 9 + w] = ru;
                red[288 + row * 9 + w] = rv;
                red[576 + row * 9 + w] = rc;
            }
        }
    __syncthreads();
    if (tid < 32) {
        const int row = tid;
        float U = 0.f, V = 0.f, C0 = 0.f;
        #pragma unroll
        for (int ww = 0; ww < 8; ++ww) {
            U  += red[row * 9 + ww];
            V  += red[288 + row * 9 + ww];
            C0 += red[576 + row * 9 + ww];
        }
        const float scl = 0.04419417382415922f;   // 1/sqrt(512)
        float mx = -3.4e38f;
        for (int s = 0; s < SSEQ; ++s)
            mx = fmaxf(mx, scl * (convW[s] * U + convB[s] * V + C0));
        float z = 0.f, a1 = 0.f, a2 = 0.f;
        for (int s = 0; s < SSEQ; ++s) {
            const float e = expf(scl * (convW[s] * U + convB[s] * V + C0) - mx);
            z += e; a1 = fmaf(e, convW[s], a1); a2 = fmaf(e, convB[s], a2);
        }
        w1s[row] = a1 / z; w2s[row] = a2 / z;
    }
    __syncthreads();

    // ---- y = q + attn_out, LN1 stats ----
    float ps[2][2] = {{0,0},{0,0}}, pq2[2][2] = {{0,0},{0,0}};
    #pragma unroll
    for (int mt = 0; mt < 2; ++mt) {
        const int rlo = mt * 16 + gid, rhi = rlo + 8;
        const float w1lo = w1s[rlo], w2lo = w2s[rlo];
        const float w1hi = w1s[rhi], w2hi = w2s[rhi];
        #pragma unroll
        for (int j = 0; j < 8; ++j)
            #pragma unroll
            for (int e = 0; e < 2; ++e) {
                const int c = w * 64 + j * 8 + 2 * tig + e;
                const float pvc = Pvb[c], wvs = g_WvSum[c], bvc = p.bv[c];
                const float y0 = acc[mt][j][e]     + fmaf(w1lo, pvc, fmaf(w2lo, wvs, bvc));
                const float y1 = acc[mt][j][2 + e] + fmaf(w1hi, pvc, fmaf(w2hi, wvs, bvc));
                acc[mt][j][e] = y0; acc[mt][j][2 + e] = y1;
                ps[mt][0] += y0; pq2[mt][0] = fmaf(y0, y0, pq2[mt][0]);
                ps[mt][1] += y1; pq2[mt][1] = fmaf(y1, y1, pq2[mt][1]);
            }
    }
    #pragma unroll
    for (int mt = 0; mt < 2; ++mt)
        #pragma unroll
        for (int h = 0; h < 2; ++h) {
            const float s1 = qred(ps[mt][h]), s2 = qred(pq2[mt][h]);
            if (tig == 0) {
                const int row = mt * 16 + h * 8 + gid;
                red[row * 9 + w] = s1;
                red[288 + row * 9 + w] = s2;
            }
        }
    __syncthreads();
    if (tid < 32) {
        float s1 = 0.f, s2 = 0.f;
        #pragma unroll
        for (int ww = 0; ww < 8; ++ww) { s1 += red[tid * 9 + ww]; s2 += red[288 + tid * 9 + ww]; }
        const float mu = s1 * (1.f / CCH);
        mus[tid] = mu;
        rss[tid] = rsqrtf(s2 * (1.f / CCH) - mu * mu + 1e-5f);
    }
    __syncthreads();
    #pragma unroll
    for (int mt = 0; mt < 2; ++mt) {
        const int rlo = mt * 16 + gid, rhi = rlo + 8;
        const float mlo = mus[rlo], slo = rss[rlo];
        const float mhi = mus[rhi], shi = rss[rhi];
        #pragma unroll
        for (int j = 0; j < 8; ++j) {
            const int cb = w * 64 + j * 8 + 2 * tig;
            const float lw0 = p.ln1_w[cb], lw1 = p.ln1_w[cb + 1];
            const float lb0 = p.ln1_b[cb], lb1 = p.ln1_b[cb + 1];
            float2 vlo = { (acc[mt][j][0] - mlo) * slo * lw0 + lb0,
                           (acc[mt][j][1] - mlo) * slo * lw1 + lb1 };
            float2 vhi = { (acc[mt][j][2] - mhi) * shi * lw0 + lb0,
                           (acc[mt][j][3] - mhi) * shi * lw1 + lb1 };
            *(float2*)(g_query + (size_t)(m0 + rlo) * CCH + cb) = vlo;
            *(float2*)(g_query + (size_t)(m0 + rhi) * CCH + cb) = vhi;
        }
    }
}

// ---------------------------------------------------------------------------
// Kernel C1: h = gelu(query@W1.T + b1)
// ---------------------------------------------------------------------------
__global__ __launch_bounds__(256, 1) void k_ffn1(Params p) {
    extern __shared__ float sm[];
    const int m0 = blockIdx.x * 32;
    const int nbase = blockIdx.y * 512;
    float acc[2][8][4];
    #pragma unroll
    for (int mt = 0; mt < 2; ++mt)
        #pragma unroll
        for (int j = 0; j < 8; ++j)
            #pragma unroll
            for (int e = 0; e < 4; ++e) acc[mt][j][e] = 0.f;

    gemm_mma<CCH>(g_query, p.W1, m0, nbase, acc, sm);

    const int lane = threadIdx.x & 31, w = threadIdx.x >> 5;
    const int gid = lane >> 2, tig = lane & 3;
    #pragma unroll
    for (int mt = 0; mt < 2; ++mt) {
        const int rlo = mt * 16 + gid, rhi = rlo + 8;
        #pragma unroll
        for (int j = 0; j < 8; ++j) {
            const int cb = nbase + w * 64 + j * 8 + 2 * tig;
            const float b0 = p.b1[cb], b1v = p.b1[cb + 1];
            float v[4] = { acc[mt][j][0] + b0, acc[mt][j][1] + b1v,
                           acc[mt][j][2] + b0, acc[mt][j][3] + b1v };
            #pragma unroll
            for (int e = 0; e < 4; ++e)
                v[e] = 0.5f * v[e] * (1.0f + erff(v[e] * 0.70710678118654752f));
            *(float2*)(g_h + (size_t)(m0 + rlo) * (2 * CCH) + cb) = make_float2(v[0], v[1]);
            *(float2*)(g_h + (size_t)(m0 + rhi) * (2 * CCH) + cb) = make_float2(v[2], v[3]);
        }
    }
}

// ---------------------------------------------------------------------------
// Kernel C2: out = LN2(query + h@W2.T + b2) + x
// ---------------------------------------------------------------------------
__global__ __launch_bounds__(256, 1) void k_ffn2(Params p, float* __restrict__ out) {
    extern __shared__ float sm[];
    const int m0 = blockIdx.x * 32;
    float acc[2][8][4];
    #pragma unroll
    for (int mt = 0; mt < 2; ++mt)
        #pragma unroll
        for (int j = 0; j < 8; ++j)
            #pragma unroll
            for (int e = 0; e < 4; ++e) acc[mt][j][e] = 0.f;

    gemm_mma<2 * CCH>(g_h, p.W2, m0, 0, acc, sm);

    const int tid = threadIdx.x;
    const int lane = tid & 31, w = tid >> 5;
    const int gid = lane >> 2, tig = lane & 3;

    float ps[2][2] = {{0,0},{0,0}}, pq2[2][2] = {{0,0},{0,0}};
    #pragma unroll
    for (int mt = 0; mt < 2; ++mt) {
        const int rlo = mt * 16 + gid, rhi = rlo + 8;
        #pragma unroll
        for (int j = 0; j < 8; ++j) {
            const int cb = w * 64 + j * 8 + 2 * tig;
            const float b20 = p.b2[cb], b21 = p.b2[cb + 1];
            const float2 qlo = *(const float2*)(g_query + (size_t)(m0 + rlo) * CCH + cb);
            const float2 qhi = *(const float2*)(g_query + (size_t)(m0 + rhi) * CCH + cb);
            const float y0 = acc[mt][j][0] + b20 + qlo.x;
            const float y1 = acc[mt][j][1] + b21 + qlo.y;
            const float y2 = acc[mt][j][2] + b20 + qhi.x;
            const float y3 = acc[mt][j][3] + b21 + qhi.y;
            acc[mt][j][0] = y0; acc[mt][j][1] = y1; acc[mt][j][2] = y2; acc[mt][j][3] = y3;
            ps[mt][0] += y0 + y1; pq2[mt][0] += y0 * y0 + y1 * y1;
            ps[mt][1] += y2 + y3; pq2[mt][1] += y2 * y2 + y3 * y3;
        }
    }
    float* red = sm;
    float* mus = sm + 640;
    float* rss = sm + 672;
    #pragma unroll
    for (int mt = 0; mt < 2; ++mt)
        #pragma unroll
        for (int h = 0; h < 2; ++h) {
            const float s1 = qred(ps[mt][h]), s2 = qred(pq2[mt][h]);
            if (tig == 0) {
                const int row = mt * 16 + h * 8 + gid;
                red[row * 9 + w] = s1;
                red[288 + row * 9 + w] = s2;
            }
        }
    __syncthreads();
    if (tid < 32) {
        float s1 = 0.f, s2 = 0.f;
        #pragma unroll
        for (int ww = 0; ww < 8; ++ww) { s1 += red[tid * 9 + ww]; s2 += red[288 + tid * 9 + ww]; }
        const float mu = s1 * (1.f / CCH);
        mus[tid] = mu;
        rss[tid] = rsqrtf(s2 * (1.f / CCH) - mu * mu + 1e-5f);
    }
    __syncthreads();
    #pragma unroll
    for (int mt = 0; mt < 2; ++mt) {
        const int rlo = mt * 16 + gid, rhi = rlo + 8;
        const float mlo = mus[rlo], slo = rss[rlo];
        const float mhi = mus[rhi], shi = rss[rhi];
        #pragma unroll
        for (int j = 0; j < 8; ++j) {
            const int cb = w * 64 + j * 8 + 2 * tig;
            const float lw0 = p.ln2_w[cb], lw1 = p.ln2_w[cb + 1];
            const float lb0 = p.ln2_b[cb], lb1 = p.ln2_b[cb + 1];
            const float2 xlo = *(const float2*)(p.x + (size_t)(m0 + rlo) * CCH + cb);
            const float2 xhi = *(const float2*)(p.x + (size_t)(m0 + rhi) * CCH + cb);
            float2 vlo = { (acc[mt][j][0] - mlo) * slo * lw0 + lb0 + xlo.x,
                           (acc[mt][j][1] - mlo) * slo * lw1 + lb1 + xlo.y };
            float2 vhi = { (acc[mt][j][2] - mhi) * shi * lw0 + lb0 + xhi.x,
                           (acc[mt][j][3] - mhi) * shi * lw1 + lb1 + xhi.y };
            *(float2*)(out + (size_t)(m0 + rlo) * CCH + cb) = vlo;
            *(float2*)(out + (size_t)(m0 + rhi) * CCH + cb) = vhi;
        }
    }
}

// ---------------------------------------------------------------------------
extern "C" void kernel_launch(void* const* d_in, const int* in_sizes, int n_in,
                              void* d_out, int out_size) {
    Params p;
    p.x        = (const float*)d_in[0];
    p.cond_emb = (const float*)d_in[1];
    p.Wq       = (const float*)d_in[2];
    p.bq       = (const float*)d_in[3];
    p.Wk       = (const float*)d_in[4];
    p.bk       = (const float*)d_in[5];
    p.Wv       = (const float*)d_in[6];
    p.bv       = (const float*)d_in[7];
    p.conv_w   = (const float*)d_in[8];
    p.conv_b   = (const float*)d_in[9];
    p.ln1_w    = (const float*)d_in[10];
    p.ln1_b    = (const float*)d_in[11];
    p.W1       = (const float*)d_in[12];
    p.b1       = (const float*)d_in[13];
    p.W2       = (const float*)d_in[14];
    p.b2       = (const float*)d_in[15];
    p.ln2_w    = (const float*)d_in[16];
    p.ln2_b    = (const float*)d_in[17];
    float* out = (float*)d_out;

    static bool attr_done = false;
    if (!attr_done) {
        cudaFuncSetAttribute(k_qattn, cudaFuncAttributeMaxDynamicSharedMemorySize, SMEM_BYTES);
        cudaFuncSetAttribute(k_ffn1,  cudaFuncAttributeMaxDynamicSharedMemorySize, SMEM_BYTES);
        cudaFuncSetAttribute(k_ffn2,  cudaFuncAttributeMaxDynamicSharedMemorySize, SMEM_BYTES);
        attr_done = true;
    }

    k_precompute<<<dim3(BB + 1, 2), 256>>>(p);
    k_qattn<<<MTOT / 32, 256, SMEM_BYTES>>>(p);
    k_ffn1<<<dim3(MTOT / 32, 2), 256, SMEM_BYTES>>>(p);
    k_ffn2<<<MTOT / 32, 256, SMEM_BYTES>>>(p, out);
}

// round 6
// speedup vs baseline: 4.8132x; 1.2224x over previous
#include <cuda_runtime.h>
#include <math.h>
#include <stdint.h>

#define BB    32
#define TT    1024
#define CCH   512
#define CONDC 256
#define LLEN  252
#define SSEQ  128
#define MTOT  (BB*TT)

// 128x128 block tile, BK=32, 3-stage cp.async, 256 threads (8 warps: 4m x 2n)
#define BK       32
#define TILE_FL  (128*BK)                 // 4096 floats per A- or B-stage
#define STAGES   3
#define SMEM_FLT (STAGES*2*TILE_FL)
#define SMEM_BYTES (SMEM_FLT*4)           // 98304 B

// Scratch (static device globals: allocation-free per harness rules)
__device__ float g_q[(size_t)MTOT * CCH];        // 64 MB (q, later reused as z)
__device__ float g_query[(size_t)MTOT * CCH];    // 64 MB
__device__ float g_h[(size_t)MTOT * 2 * CCH];    // 128 MB
__device__ float g_Pk[BB * CCH];
__device__ float g_Pv[BB * CCH];
__device__ float g_WkSum[CCH];
__device__ float g_WvSum[CCH];

struct Params {
    const float *x, *cond_emb, *Wq, *bq, *Wk, *bk, *Wv, *bv,
                *conv_w, *conv_b, *ln1_w, *ln1_b, *W1, *b1, *W2, *b2,
                *ln2_w, *ln2_b;
};

// ---------------------------------------------------------------------------
// primitives
// ---------------------------------------------------------------------------
__device__ __forceinline__ void mma8(float* c, uint32_t a0, uint32_t a1,
                                     uint32_t a2, uint32_t a3,
                                     uint32_t b0, uint32_t b1) {
    asm volatile(
        "mma.sync.aligned.m16n8k8.row.col.f32.tf32.tf32.f32 "
        "{%0,%1,%2,%3}, {%4,%5,%6,%7}, {%8,%9}, {%0,%1,%2,%3};\n"
        : "+f"(c[0]), "+f"(c[1]), "+f"(c[2]), "+f"(c[3])
        : "r"(a0), "r"(a1), "r"(a2), "r"(a3), "r"(b0), "r"(b1));
}

__device__ __forceinline__ void cpa(float* dst, const float* src) {
    unsigned d = (unsigned)__cvta_generic_to_shared(dst);
    asm volatile("cp.async.cg.shared.global [%0], [%1], 16;\n" :: "r"(d), "l"(src));
}
#define CP_COMMIT() asm volatile("cp.async.commit_group;\n")
template<int N> __device__ __forceinline__ void waitg() {
    asm volatile("cp.async.wait_group %0;\n" :: "n"(N));
}

__device__ __forceinline__ float wsum(float v) {
    #pragma unroll
    for (int o = 16; o; o >>= 1) v += __shfl_xor_sync(0xffffffffu, v, o);
    return v;
}
__device__ __forceinline__ float wmax(float v) {
    #pragma unroll
    for (int o = 16; o; o >>= 1) v = fmaxf(v, __shfl_xor_sync(0xffffffffu, v, o));
    return v;
}

// ---------------------------------------------------------------------------
// Stage one 128x32 A-tile and 128x32 B-tile into smem.
// Swizzle: phys float4 slot = u ^ (row&7)  -> conflict-free st & frag ld.
// ---------------------------------------------------------------------------
__device__ __forceinline__ void load_tile(float* As, float* Bs,
                                          const float* __restrict__ A,
                                          const float* __restrict__ Bw,
                                          int K, int k0, int tid) {
    const int u  = tid & 7;
    const int r0 = tid >> 3;                    // 0..31
    #pragma unroll
    for (int i = 0; i < 4; ++i) {
        const int r  = i * 32 + r0;
        const int ph = r * BK + 4 * (u ^ (r & 7));
        cpa(As + ph, A  + (size_t)r * K + k0 + 4 * u);
        cpa(Bs + ph, Bw + (size_t)r * K + k0 + 4 * u);
    }
}

// ---------------------------------------------------------------------------
// GEMM: out[m0:+128, nbase:+128] = inp @ wgt^T (wgt row-major [N,K])
// EPI: 0 = raw store, 1 = +bias then exact GELU
// ---------------------------------------------------------------------------
template<int KDIM, int EPI>
__global__ __launch_bounds__(256, 2) void k_gemm(
    const float* __restrict__ inp, const float* __restrict__ wgt,
    const float* __restrict__ bias, float* __restrict__ out, int Nout)
{
    extern __shared__ float sm[];
    const int tid  = threadIdx.x;
    const int lane = tid & 31, w = tid >> 5;
    const int wm = w & 3, wn = w >> 2;
    const int gid = lane >> 2, tig = lane & 3;
    const int xs = 4 * gid;
    const int m0 = blockIdx.x * 128;
    const int nbase = blockIdx.y * 128;
    const float* A  = inp + (size_t)m0 * KDIM;
    const float* Bw = wgt + (size_t)nbase * KDIM;

    float acc[2][8][4];
    #pragma unroll
    for (int mt = 0; mt < 2; ++mt)
        #pragma unroll
        for (int j = 0; j < 8; ++j)
            #pragma unroll
            for (int e = 0; e < 4; ++e) acc[mt][j][e] = 0.f;

    constexpr int NT = KDIM / BK;
    load_tile(sm,               sm + TILE_FL,               A, Bw, KDIM, 0,  tid); CP_COMMIT();
    load_tile(sm + 2 * TILE_FL, sm + 3 * TILE_FL,           A, Bw, KDIM, BK, tid); CP_COMMIT();

    int cs = 0, ls = 2;                         // compute stage, next load stage
    #pragma unroll 1
    for (int t = 0; t < NT; ++t) {
        if (t + 1 < NT) waitg<1>(); else waitg<0>();
        __syncthreads();
        const float* Ast = sm + cs * 2 * TILE_FL;
        const float* Bst = Ast + TILE_FL;

        #pragma unroll
        for (int ks = 0; ks < 4; ++ks) {
            const int kk0 = ks * 8;
            uint32_t b0[8], b1[8];
            #pragma unroll
            for (int j = 0; j < 8; ++j) {
                const float* bp = Bst + (wn * 64 + j * 8 + gid) * BK;
                b0[j] = __float_as_uint(bp[(kk0 + tig)     ^ xs]);
                b1[j] = __float_as_uint(bp[(kk0 + tig + 4) ^ xs]);
            }
            #pragma unroll
            for (int mt = 0; mt < 2; ++mt) {
                const float* apl = Ast + (wm * 32 + mt * 16 + gid) * BK;
                const float* aph = apl + 8 * BK;
                const uint32_t a0 = __float_as_uint(apl[(kk0 + tig)     ^ xs]);
                const uint32_t a1 = __float_as_uint(aph[(kk0 + tig)     ^ xs]);
                const uint32_t a2 = __float_as_uint(apl[(kk0 + tig + 4) ^ xs]);
                const uint32_t a3 = __float_as_uint(aph[(kk0 + tig + 4) ^ xs]);
                #pragma unroll
                for (int j = 0; j < 8; ++j)
                    mma8(acc[mt][j], a0, a1, a2, a3, b0[j], b1[j]);
            }
        }
        if (t + 2 < NT) {
            float* Ad = sm + ls * 2 * TILE_FL;
            load_tile(Ad, Ad + TILE_FL, A, Bw, KDIM, (t + 2) * BK, tid);
            CP_COMMIT();
        }
        if (++cs == STAGES) cs = 0;
        if (++ls == STAGES) ls = 0;
    }

    // epilogue
    #pragma unroll
    for (int mt = 0; mt < 2; ++mt)
        #pragma unroll
        for (int half = 0; half < 2; ++half) {
            const int row = m0 + wm * 32 + mt * 16 + half * 8 + gid;
            #pragma unroll
            for (int j = 0; j < 8; ++j) {
                const int c = nbase + wn * 64 + j * 8 + 2 * tig;
                float v0 = acc[mt][j][half * 2 + 0];
                float v1 = acc[mt][j][half * 2 + 1];
                if (EPI == 1) {
                    v0 += bias[c]; v1 += bias[c + 1];
                    v0 = 0.5f * v0 * (1.0f + erff(v0 * 0.70710678118654752f));
                    v1 = 0.5f * v1 * (1.0f + erff(v1 * 0.70710678118654752f));
                }
                *(float2*)(out + (size_t)row * Nout + c) = make_float2(v0, v1);
            }
        }
}

// ---------------------------------------------------------------------------
// Precompute: Pk[b,c] = pad[b]·Wk[c,:], Pv likewise; plus weight row-sums
// ---------------------------------------------------------------------------
__global__ void k_precompute(Params p) {
    __shared__ float padS[CONDC];
    const int bb = blockIdx.x;
    const int which = blockIdx.y;
    const float* W = which ? p.Wv : p.Wk;

    if (bb == BB) {
        for (int c = threadIdx.x; c < CCH; c += blockDim.x) {
            float s = 0.f;
            const float* wr = W + (size_t)c * CONDC;
            #pragma unroll 4
            for (int j = 0; j < CONDC; ++j) s += wr[j];
            (which ? g_WvSum : g_WkSum)[c] = s;
        }
        return;
    }
    for (int j = threadIdx.x; j < CONDC; j += blockDim.x) {
        int src = (j + LLEN - 2) % LLEN;
        padS[j] = p.cond_emb[bb * LLEN + src];
    }
    __syncthreads();
    for (int c = threadIdx.x; c < CCH; c += blockDim.x) {
        float s = 0.f;
        const float* wr = W + (size_t)c * CONDC;
        #pragma unroll 4
        for (int j = 0; j < CONDC; ++j) s = fmaf(padS[j], wr[j], s);
        (which ? g_Pv : g_Pk)[bb * CCH + c] = s;
    }
}

// ---------------------------------------------------------------------------
// Warp-per-row: q=g_q+bq -> rank-1 attention -> +LN1 -> g_query
// ---------------------------------------------------------------------------
__global__ __launch_bounds__(256) void k_attn_ln1(Params p) {
    __shared__ float convW[SSEQ], convB[SSEQ];
    const int tid = threadIdx.x;
    if (tid < SSEQ) { convW[tid] = p.conv_w[tid]; convB[tid] = p.conv_b[tid]; }
    __syncthreads();

    const int lane = tid & 31, w = tid >> 5;
    const int row = blockIdx.x * 8 + w;
    const int b = row >> 10;                        // row / TT
    const float* qr  = g_q + (size_t)row * CCH;
    const float* Pkb = g_Pk + b * CCH;
    const float* Pvb = g_Pv + b * CCH;

    float qv[16];
    float u = 0.f, vv = 0.f, c0 = 0.f;
    #pragma unroll
    for (int j = 0; j < 16; ++j) {
        const int c = lane + 32 * j;
        const float q = qr[c] + p.bq[c];
        qv[j] = q;
        u  = fmaf(q, Pkb[c],    u);
        vv = fmaf(q, g_WkSum[c], vv);
        c0 = fmaf(q, p.bk[c],   c0);
    }
    u = wsum(u); vv = wsum(vv); c0 = wsum(c0);

    const float scl = 0.04419417382415922f;         // 1/sqrt(512)
    float sc[4], mx = -3.4e38f;
    #pragma unroll
    for (int ss = 0; ss < 4; ++ss) {
        const int s = lane + 32 * ss;
        sc[ss] = scl * (convW[s] * u + convB[s] * vv + c0);
        mx = fmaxf(mx, sc[ss]);
    }
    mx = wmax(mx);
    float z = 0.f, a1 = 0.f, a2 = 0.f;
    #pragma unroll
    for (int ss = 0; ss < 4; ++ss) {
        const int s = lane + 32 * ss;
        const float e = expf(sc[ss] - mx);
        z += e; a1 = fmaf(e, convW[s], a1); a2 = fmaf(e, convB[s], a2);
    }
    z = wsum(z); a1 = wsum(a1); a2 = wsum(a2);
    const float w1 = a1 / z, w2 = a2 / z;

    float s1 = 0.f, s2 = 0.f;
    #pragma unroll
    for (int j = 0; j < 16; ++j) {
        const int c = lane + 32 * j;
        const float y = qv[j] + fmaf(w1, Pvb[c], fmaf(w2, g_WvSum[c], p.bv[c]));
        qv[j] = y;
        s1 += y; s2 = fmaf(y, y, s2);
    }
    s1 = wsum(s1); s2 = wsum(s2);
    const float mu = s1 * (1.f / CCH);
    const float rs = rsqrtf(s2 * (1.f / CCH) - mu * mu + 1e-5f);
    float* qo = g_query + (size_t)row * CCH;
    #pragma unroll
    for (int j = 0; j < 16; ++j) {
        const int c = lane + 32 * j;
        qo[c] = (qv[j] - mu) * rs * p.ln1_w[c] + p.ln1_b[c];
    }
}

// ---------------------------------------------------------------------------
// Warp-per-row: out = LN2(z + b2 + query) + x   (z lives in g_q)
// ---------------------------------------------------------------------------
__global__ __launch_bounds__(256) void k_ln2(Params p, float* __restrict__ out) {
    const int tid = threadIdx.x;
    const int lane = tid & 31, w = tid >> 5;
    const int row = blockIdx.x * 8 + w;
    const float* zr = g_q     + (size_t)row * CCH;
    const float* qr = g_query + (size_t)row * CCH;
    const float* xr = p.x     + (size_t)row * CCH;

    float yv[16];
    float s1 = 0.f, s2 = 0.f;
    #pragma unroll
    for (int j = 0; j < 16; ++j) {
        const int c = lane + 32 * j;
        const float y = zr[c] + p.b2[c] + qr[c];
        yv[j] = y;
        s1 += y; s2 = fmaf(y, y, s2);
    }
    s1 = wsum(s1); s2 = wsum(s2);
    const float mu = s1 * (1.f / CCH);
    const float rs = rsqrtf(s2 * (1.f / CCH) - mu * mu + 1e-5f);
    float* orow = out + (size_t)row * CCH;
    #pragma unroll
    for (int j = 0; j < 16; ++j) {
        const int c = lane + 32 * j;
        orow[c] = (yv[j] - mu) * rs * p.ln2_w[c] + p.ln2_b[c] + xr[c];
    }
}

// ---------------------------------------------------------------------------
extern "C" void kernel_launch(void* const* d_in, const int* in_sizes, int n_in,
                              void* d_out, int out_size) {
    Params p;
    p.x        = (const float*)d_in[0];
    p.cond_emb = (const float*)d_in[1];
    p.Wq       = (const float*)d_in[2];
    p.bq       = (const float*)d_in[3];
    p.Wk       = (const float*)d_in[4];
    p.bk       = (const float*)d_in[5];
    p.Wv       = (const float*)d_in[6];
    p.bv       = (const float*)d_in[7];
    p.conv_w   = (const float*)d_in[8];
    p.conv_b   = (const float*)d_in[9];
    p.ln1_w    = (const float*)d_in[10];
    p.ln1_b    = (const float*)d_in[11];
    p.W1       = (const float*)d_in[12];
    p.b1       = (const float*)d_in[13];
    p.W2       = (const float*)d_in[14];
    p.b2       = (const float*)d_in[15];
    p.ln2_w    = (const float*)d_in[16];
    p.ln2_b    = (const float*)d_in[17];
    float* out = (float*)d_out;

    static bool attr_done = false;
    if (!attr_done) {
        cudaFuncSetAttribute(k_gemm<512, 0>,  cudaFuncAttributeMaxDynamicSharedMemorySize, SMEM_BYTES);
        cudaFuncSetAttribute(k_gemm<512, 1>,  cudaFuncAttributeMaxDynamicSharedMemorySize, SMEM_BYTES);
        cudaFuncSetAttribute(k_gemm<1024, 0>, cudaFuncAttributeMaxDynamicSharedMemorySize, SMEM_BYTES);
        attr_done = true;
    }

    float* q_buf = nullptr;  // device-symbol addresses resolved at kernel level
    (void)q_buf;

    k_precompute<<<dim3(BB + 1, 2), 256>>>(p);

    // q = x @ Wq^T  (raw, bias folded into attn kernel)
    {
        float* dq; cudaGetSymbolAddress((void**)&dq, g_q);
        k_gemm<512, 0><<<dim3(MTOT / 128, 4), 256, SMEM_BYTES>>>(p.x, p.Wq, nullptr, dq, CCH);
    }
    k_attn_ln1<<<MTOT / 8, 256>>>(p);

    // h = gelu(query @ W1^T + b1)
    {
        float *dqry, *dh;
        cudaGetSymbolAddress((void**)&dqry, g_query);
        cudaGetSymbolAddress((void**)&dh, g_h);
        k_gemm<512, 1><<<dim3(MTOT / 128, 8), 256, SMEM_BYTES>>>(dqry, p.W1, p.b1, dh, 2 * CCH);
        // z = h @ W2^T  (raw, bias in ln2) -> reuse g_q
        float* dz; cudaGetSymbolAddress((void**)&dz, g_q);
        k_gemm<1024, 0><<<dim3(MTOT / 128, 4), 256, SMEM_BYTES>>>(dh, p.W2, nullptr, dz, CCH);
    }
    k_ln2<<<MTOT / 8, 256>>>(p, out);
}

// round 10
// speedup vs baseline: 6.8331x; 1.4197x over previous
#include <cuda_runtime.h>
#include <cuda_fp16.h>
#include <math.h>
#include <stdint.h>

#define BB    32
#define TT    1024
#define CCH   512
#define CONDC 256
#define LLEN  252
#define SSEQ  128
#define MTOT  (BB*TT)

// fp16 GEMM: 128x128 block tile, BK=64, 3-stage cp.async, 256 thr (8 warps 4m x 2n)
#define BK        64
#define TILE_BYTES (128*128)              // 128 rows x 64 halves = 16 KB (A or B)
#define STAGE_BYTES (2*TILE_BYTES)        // 32 KB
#define STAGES    3
#define SMEM_BYTES (STAGES*STAGE_BYTES)   // 96 KB

// Scratch (static device globals: allocation-free per harness rules)
__device__ float  g_q[(size_t)MTOT * CCH];          // q fp32, later reused as z
__device__ float  g_query[(size_t)MTOT * CCH];      // fp32 (LN2 residual)
__device__ __half g_xh[(size_t)MTOT * CCH];
__device__ __half g_qh[(size_t)MTOT * CCH];         // half(query)
__device__ __half g_hh[(size_t)MTOT * 2 * CCH];     // half(h)
__device__ __half g_Wqh[CCH * CCH];
__device__ __half g_W1h[2 * CCH * CCH];
__device__ __half g_W2h[2 * CCH * CCH];
__device__ float g_Pk[BB * CCH];
__device__ float g_Pv[BB * CCH];
__device__ float g_WkSum[CCH];
__device__ float g_WvSum[CCH];

struct Params {
    const float *x, *cond_emb, *Wq, *bq, *Wk, *bk, *Wv, *bv,
                *conv_w, *conv_b, *ln1_w, *ln1_b, *W1, *b1, *W2, *b2,
                *ln2_w, *ln2_b;
};

// ---------------------------------------------------------------------------
// primitives
// ---------------------------------------------------------------------------
__device__ __forceinline__ void mma16(float* c, const uint32_t* a, const uint32_t* b) {
    asm volatile(
        "mma.sync.aligned.m16n8k16.row.col.f32.f16.f16.f32 "
        "{%0,%1,%2,%3}, {%4,%5,%6,%7}, {%8,%9}, {%0,%1,%2,%3};\n"
        : "+f"(c[0]), "+f"(c[1]), "+f"(c[2]), "+f"(c[3])
        : "r"(a[0]), "r"(a[1]), "r"(a[2]), "r"(a[3]), "r"(b[0]), "r"(b[1]));
}
__device__ __forceinline__ void ldsm4(uint32_t* r, uint32_t addr) {
    asm volatile("ldmatrix.sync.aligned.m8n8.x4.shared.b16 {%0,%1,%2,%3}, [%4];"
                 : "=r"(r[0]), "=r"(r[1]), "=r"(r[2]), "=r"(r[3]) : "r"(addr));
}
__device__ __forceinline__ void cpa(void* dst, const void* src) {
    unsigned d = (unsigned)__cvta_generic_to_shared(dst);
    asm volatile("cp.async.cg.shared.global [%0], [%1], 16;\n" :: "r"(d), "l"(src));
}
#define CP_COMMIT() asm volatile("cp.async.commit_group;\n")
template<int N> __device__ __forceinline__ void waitg() {
    asm volatile("cp.async.wait_group %0;\n" :: "n"(N));
}
__device__ __forceinline__ float wsum(float v) {
    #pragma unroll
    for (int o = 16; o; o >>= 1) v += __shfl_xor_sync(0xffffffffu, v, o);
    return v;
}
__device__ __forceinline__ float wmax(float v) {
    #pragma unroll
    for (int o = 16; o; o >>= 1) v = fmaxf(v, __shfl_xor_sync(0xffffffffu, v, o));
    return v;
}

// ---------------------------------------------------------------------------
// Stage 128x64h A-tile and B-tile: row = 128B, chunk u(0..7), phys = u^(r&7)
// ---------------------------------------------------------------------------
__device__ __forceinline__ void load_tile_h(char* stage,
                                            const __half* __restrict__ A,
                                            const __half* __restrict__ Bw,
                                            int K, int k0, int tid) {
    const int u = tid & 7, r0 = tid >> 3;            // r0: 0..31
    char* As = stage;
    char* Bs = stage + TILE_BYTES;
    #pragma unroll
    for (int i = 0; i < 4; ++i) {
        const int r  = i * 32 + r0;
        const int ph = r * 128 + 16 * (u ^ (r & 7));
        cpa(As + ph, A  + (size_t)r * K + k0 + 8 * u);
        cpa(Bs + ph, Bw + (size_t)r * K + k0 + 8 * u);
    }
}

// ---------------------------------------------------------------------------
// fp16 GEMM: out[m0:+128, nbase:+128] = inp @ wgt^T  (both half, K-major)
// EPI: 0 = raw fp32 store, 1 = +bias, exact GELU, half store
// ---------------------------------------------------------------------------
template<int KDIM, int EPI>
__global__ __launch_bounds__(256, 2) void k_gemm_h(
    const __half* __restrict__ inp, const __half* __restrict__ wgt,
    const float* __restrict__ bias, void* __restrict__ outv, int Nout)
{
    extern __shared__ char sm[];
    const uint32_t smb = (uint32_t)__cvta_generic_to_shared(sm);
    const int tid  = threadIdx.x;
    const int lane = tid & 31, w = tid >> 5;
    const int wm = w & 3, wn = w >> 2;
    const int gid = lane >> 2, tig = lane & 3;
    const int m0 = blockIdx.x * 128, nbase = blockIdx.y * 128;
    const __half* A  = inp + (size_t)m0 * KDIM;
    const __half* Bw = wgt + (size_t)nbase * KDIM;

    float acc[2][8][4];
    #pragma unroll
    for (int mt = 0; mt < 2; ++mt)
        #pragma unroll
        for (int j = 0; j < 8; ++j)
            #pragma unroll
            for (int e = 0; e < 4; ++e) acc[mt][j][e] = 0.f;

    // per-lane ldmatrix row geometry (offsets within a stage)
    const int arow0 = wm * 32 + (lane & 15);          // A rows for mt=0 (mt adds 16)
    const uint32_t aoffA0 = arow0 * 128;
    const uint32_t aoffA1 = (arow0 + 16) * 128;
    const int aswz0 = arow0 & 7, aswz1 = (arow0 + 16) & 7;
    const int achunk = lane >> 4;                     // +0 or +1 16B chunk

    const int q = lane >> 3;
    const int brow0 = wn * 64 + (q >> 1) * 8 + (lane & 7);  // jp adds 16
    const int bchunk = q & 1;

    constexpr int NT = KDIM / BK;
    load_tile_h(sm + 0 * STAGE_BYTES, A, Bw, KDIM, 0 * BK, tid); CP_COMMIT();
    load_tile_h(sm + 1 * STAGE_BYTES, A, Bw, KDIM, 1 * BK, tid); CP_COMMIT();

    int cs = 0, ls = 2;
    #pragma unroll 1
    for (int t = 0; t < NT; ++t) {
        if (t + 1 < NT) waitg<1>(); else waitg<0>();
        __syncthreads();
        const uint32_t Ast = smb + cs * STAGE_BYTES;
        const uint32_t Bst = Ast + TILE_BYTES;

        #pragma unroll
        for (int ks = 0; ks < 4; ++ks) {
            const int c0 = 2 * ks;                    // 16B-chunk base for this k16
            uint32_t a[2][4];
            ldsm4(a[0], Ast + aoffA0 + 16 * ((c0 + achunk) ^ aswz0));
            ldsm4(a[1], Ast + aoffA1 + 16 * ((c0 + achunk) ^ aswz1));
            uint32_t b[8][2];
            #pragma unroll
            for (int jp = 0; jp < 4; ++jp) {
                const int br = brow0 + jp * 16;
                uint32_t r4[4];
                ldsm4(r4, Bst + br * 128 + 16 * ((c0 + bchunk) ^ (br & 7)));
                b[2 * jp][0] = r4[0]; b[2 * jp][1] = r4[1];
                b[2 * jp + 1][0] = r4[2]; b[2 * jp + 1][1] = r4[3];
            }
            #pragma unroll
            for (int mt = 0; mt < 2; ++mt)
                #pragma unroll
                for (int j = 0; j < 8; ++j)
                    mma16(acc[mt][j], a[mt], b[j]);
        }
        if (t + 2 < NT) {
            load_tile_h(sm + ls * STAGE_BYTES, A, Bw, KDIM, (t + 2) * BK, tid);
            CP_COMMIT();
        }
        if (++cs == STAGES) cs = 0;
        if (++ls == STAGES) ls = 0;
    }

    // epilogue: row = m0 + wm*32 + mt*16 + half*8 + gid ; col = nbase + wn*64 + j*8 + 2*tig
    #pragma unroll
    for (int mt = 0; mt < 2; ++mt)
        #pragma unroll
        for (int half = 0; half < 2; ++half) {
            const int row = m0 + wm * 32 + mt * 16 + half * 8 + gid;
            #pragma unroll
            for (int j = 0; j < 8; ++j) {
                const int c = nbase + wn * 64 + j * 8 + 2 * tig;
                float v0 = acc[mt][j][half * 2 + 0];
                float v1 = acc[mt][j][half * 2 + 1];
                if (EPI == 1) {
                    v0 += bias[c]; v1 += bias[c + 1];
                    v0 = 0.5f * v0 * (1.0f + erff(v0 * 0.70710678118654752f));
                    v1 = 0.5f * v1 * (1.0f + erff(v1 * 0.70710678118654752f));
                    *(__half2*)((__half*)outv + (size_t)row * Nout + c) =
                        __floats2half2_rn(v0, v1);
                } else {
                    *(float2*)((float*)outv + (size_t)row * Nout + c) =
                        make_float2(v0, v1);
                }
            }
        }
}

// ---------------------------------------------------------------------------
// fp32 -> fp16 conversion (vectorized by 4)
// ---------------------------------------------------------------------------
__global__ void k_f2h(const float* __restrict__ in, __half* __restrict__ out, int n4) {
    const int i = blockIdx.x * blockDim.x + threadIdx.x;
    if (i < n4) {
        const float4 v = ((const float4*)in)[i];
        __half2 h0 = __floats2half2_rn(v.x, v.y);
        __half2 h1 = __floats2half2_rn(v.z, v.w);
        ((__half2*)out)[2 * i]     = h0;
        ((__half2*)out)[2 * i + 1] = h1;
    }
}

// ---------------------------------------------------------------------------
// Precompute: Pk[b,c] = pad[b]·Wk[c,:], Pv likewise; plus weight row-sums
// ---------------------------------------------------------------------------
__global__ void k_precompute(Params p) {
    __shared__ float padS[CONDC];
    const int bb = blockIdx.x;
    const int which = blockIdx.y;
    const float* W = which ? p.Wv : p.Wk;

    if (bb == BB) {
        for (int c = threadIdx.x; c < CCH; c += blockDim.x) {
            float s = 0.f;
            const float* wr = W + (size_t)c * CONDC;
            #pragma unroll 4
            for (int j = 0; j < CONDC; ++j) s += wr[j];
            (which ? g_WvSum : g_WkSum)[c] = s;
        }
        return;
    }
    for (int j = threadIdx.x; j < CONDC; j += blockDim.x) {
        int src = (j + LLEN - 2) % LLEN;
        padS[j] = p.cond_emb[bb * LLEN + src];
    }
    __syncthreads();
    for (int c = threadIdx.x; c < CCH; c += blockDim.x) {
        float s = 0.f;
        const float* wr = W + (size_t)c * CONDC;
        #pragma unroll 4
        for (int j = 0; j < CONDC; ++j) s = fmaf(padS[j], wr[j], s);
        (which ? g_Pv : g_Pk)[bb * CCH + c] = s;
    }
}

// ---------------------------------------------------------------------------
// Warp-per-row: q=g_q+bq -> rank-1 attention -> +LN1 -> g_query (f32) + g_qh (f16)
// ---------------------------------------------------------------------------
__global__ __launch_bounds__(256) void k_attn_ln1(Params p) {
    __shared__ float convW[SSEQ], convB[SSEQ];
    const int tid = threadIdx.x;
    if (tid < SSEQ) { convW[tid] = p.conv_w[tid]; convB[tid] = p.conv_b[tid]; }
    __syncthreads();

    const int lane = tid & 31, w = tid >> 5;
    const int row = blockIdx.x * 8 + w;
    const int b = row >> 10;
    const float* qr  = g_q + (size_t)row * CCH;
    const float* Pkb = g_Pk + b * CCH;
    const float* Pvb = g_Pv + b * CCH;

    float qv[16];
    float u = 0.f, vv = 0.f, c0 = 0.f;
    #pragma unroll
    for (int j = 0; j < 16; ++j) {
        const int c = lane + 32 * j;
        const float q = qr[c] + p.bq[c];
        qv[j] = q;
        u  = fmaf(q, Pkb[c],     u);
        vv = fmaf(q, g_WkSum[c], vv);
        c0 = fmaf(q, p.bk[c],    c0);
    }
    u = wsum(u); vv = wsum(vv); c0 = wsum(c0);

    const float scl = 0.04419417382415922f;
    float sc[4], mx = -3.4e38f;
    #pragma unroll
    for (int ss = 0; ss < 4; ++ss) {
        const int s = lane + 32 * ss;
        sc[ss] = scl * (convW[s] * u + convB[s] * vv + c0);
        mx = fmaxf(mx, sc[ss]);
    }
    mx = wmax(mx);
    float z = 0.f, a1 = 0.f, a2 = 0.f;
    #pragma unroll
    for (int ss = 0; ss < 4; ++ss) {
        const int s = lane + 32 * ss;
        const float e = expf(sc[ss] - mx);
        z += e; a1 = fmaf(e, convW[s], a1); a2 = fmaf(e, convB[s], a2);
    }
    z = wsum(z); a1 = wsum(a1); a2 = wsum(a2);
    const float w1 = a1 / z, w2 = a2 / z;

    float s1 = 0.f, s2 = 0.f;
    #pragma unroll
    for (int j = 0; j < 16; ++j) {
        const int c = lane + 32 * j;
        const float y = qv[j] + fmaf(w1, Pvb[c], fmaf(w2, g_WvSum[c], p.bv[c]));
        qv[j] = y;
        s1 += y; s2 = fmaf(y, y, s2);
    }
    s1 = wsum(s1); s2 = wsum(s2);
    const float mu = s1 * (1.f / CCH);
    const float rs = rsqrtf(s2 * (1.f / CCH) - mu * mu + 1e-5f);
    float*  qo  = g_query + (size_t)row * CCH;
    __half* qoh = g_qh    + (size_t)row * CCH;
    #pragma unroll
    for (int j = 0; j < 16; ++j) {
        const int c = lane + 32 * j;
        const float o = (qv[j] - mu) * rs * p.ln1_w[c] + p.ln1_b[c];
        qo[c]  = o;
        qoh[c] = __float2half_rn(o);
    }
}

// ---------------------------------------------------------------------------
// Warp-per-row: out = LN2(z + b2 + query) + x   (z lives in g_q)
// ---------------------------------------------------------------------------
__global__ __launch_bounds__(256) void k_ln2(Params p, float* __restrict__ out) {
    const int tid = threadIdx.x;
    const int lane = tid & 31, w = tid >> 5;
    const int row = blockIdx.x * 8 + w;
    const float* zr = g_q     + (size_t)row * CCH;
    const float* qr = g_query + (size_t)row * CCH;
    const float* xr = p.x     + (size_t)row * CCH;

    float yv[16];
    float s1 = 0.f, s2 = 0.f;
    #pragma unroll
    for (int j = 0; j < 16; ++j) {
        const int c = lane + 32 * j;
        const float y = zr[c] + p.b2[c] + qr[c];
        yv[j] = y;
        s1 += y; s2 = fmaf(y, y, s2);
    }
    s1 = wsum(s1); s2 = wsum(s2);
    const float mu = s1 * (1.f / CCH);
    const float rs = rsqrtf(s2 * (1.f / CCH) - mu * mu + 1e-5f);
    float* orow = out + (size_t)row * CCH;
    #pragma unroll
    for (int j = 0; j < 16; ++j) {
        const int c = lane + 32 * j;
        orow[c] = (yv[j] - mu) * rs * p.ln2_w[c] + p.ln2_b[c] + xr[c];
    }
}

// ---------------------------------------------------------------------------
extern "C" void kernel_launch(void* const* d_in, const int* in_sizes, int n_in,
                              void* d_out, int out_size) {
    Params p;
    p.x        = (const float*)d_in[0];
    p.cond_emb = (const float*)d_in[1];
    p.Wq       = (const float*)d_in[2];
    p.bq       = (const float*)d_in[3];
    p.Wk       = (const float*)d_in[4];
    p.bk       = (const float*)d_in[5];
    p.Wv       = (const float*)d_in[6];
    p.bv       = (const float*)d_in[7];
    p.conv_w   = (const float*)d_in[8];
    p.conv_b   = (const float*)d_in[9];
    p.ln1_w    = (const float*)d_in[10];
    p.ln1_b    = (const float*)d_in[11];
    p.W1       = (const float*)d_in[12];
    p.b1       = (const float*)d_in[13];
    p.W2       = (const float*)d_in[14];
    p.b2       = (const float*)d_in[15];
    p.ln2_w    = (const float*)d_in[16];
    p.ln2_b    = (const float*)d_in[17];
    float* out = (float*)d_out;

    static bool attr_done = false;
    if (!attr_done) {
        cudaFuncSetAttribute(k_gemm_h<512, 0>,  cudaFuncAttributeMaxDynamicSharedMemorySize, SMEM_BYTES);
        cudaFuncSetAttribute(k_gemm_h<512, 1>,  cudaFuncAttributeMaxDynamicSharedMemorySize, SMEM_BYTES);
        cudaFuncSetAttribute(k_gemm_h<1024, 0>, cudaFuncAttributeMaxDynamicSharedMemorySize, SMEM_BYTES);
        attr_done = true;
    }

    float *dq;
    __half *dxh, *dqh, *dhh, *dWqh, *dW1h, *dW2h;
    cudaGetSymbolAddress((void**)&dq,   g_q);
    cudaGetSymbolAddress((void**)&dxh,  g_xh);
    cudaGetSymbolAddress((void**)&dqh,  g_qh);
    cudaGetSymbolAddress((void**)&dhh,  g_hh);
    cudaGetSymbolAddress((void**)&dWqh, g_Wqh);
    cudaGetSymbolAddress((void**)&dW1h, g_W1h);
    cudaGetSymbolAddress((void**)&dW2h, g_W2h);

    k_precompute<<<dim3(BB + 1, 2), 256>>>(p);

    // fp32 -> fp16 conversions
    {
        const int nx = MTOT * CCH / 4;
        k_f2h<<<(nx + 255) / 256, 256>>>(p.x, dxh, nx);
        const int nwq = CCH * CCH / 4;
        k_f2h<<<(nwq + 255) / 256, 256>>>(p.Wq, dWqh, nwq);
        const int nw1 = 2 * CCH * CCH / 4;
        k_f2h<<<(nw1 + 255) / 256, 256>>>(p.W1, dW1h, nw1);
        const int nw2 = 2 * CCH * CCH / 4;
        k_f2h<<<(nw2 + 255) / 256, 256>>>(p.W2, dW2h, nw2);
    }

    // q = x @ Wq^T (fp32 out; bias folded into attn kernel)
    k_gemm_h<512, 0><<<dim3(MTOT / 128, 4), 256, SMEM_BYTES>>>(dxh, dWqh, nullptr, dq, CCH);
    k_attn_ln1<<<MTOT / 8, 256>>>(p);
    // h = gelu(query @ W1^T + b1) (half out)
    k_gemm_h<512, 1><<<dim3(MTOT / 128, 8), 256, SMEM_BYTES>>>(dqh, dW1h, p.b1, dhh, 2 * CCH);
    // z = h @ W2^T (fp32 out; bias in ln2) -> reuse g_q
    k_gemm_h<1024, 0><<<dim3(MTOT / 128, 4), 256, SMEM_BYTES>>>(dhh, dW2h, nullptr, dq, CCH);
    k_ln2<<<MTOT / 8, 256>>>(p, out);
}

// round 13
// speedup vs baseline: 7.4232x; 1.0864x over previous
#include <cuda_runtime.h>
#include <cuda_fp16.h>
#include <math.h>
#include <stdint.h>

#define BB    32
#define TT    1024
#define CCH   512
#define CONDC 256
#define LLEN  252
#define SSEQ  128
#define MTOT  (BB*TT)

// fp16 GEMM: 128x128 block tile, BK=64, 3-stage cp.async, 256 thr (8 warps 4m x 2n)
#define BK        64
#define TILE_BYTES (128*128)              // 128 rows x 64 halves = 16 KB (A or B)
#define STAGE_BYTES (2*TILE_BYTES)        // 32 KB
#define STAGES    3
#define SMEM_BYTES (STAGES*STAGE_BYTES)   // 96 KB

// Scratch (static device globals: allocation-free per harness rules)
__device__ float  g_q[(size_t)MTOT * CCH];          // q fp32, later reused as z
__device__ float  g_query[(size_t)MTOT * CCH];      // fp32 (LN2 residual)
__device__ __half g_xh[(size_t)MTOT * CCH];
__device__ __half g_qh[(size_t)MTOT * CCH];         // half(query)
__device__ __half g_hh[(size_t)MTOT * 2 * CCH];     // half(h)
__device__ __half g_Wqh[CCH * CCH];
__device__ __half g_W1h[2 * CCH * CCH];
__device__ __half g_W2h[2 * CCH * CCH];
__device__ float g_Pk[BB * CCH];
__device__ float g_Pv[BB * CCH];
__device__ float g_WkSum[CCH];
__device__ float g_WvSum[CCH];

struct Params {
    const float *x, *cond_emb, *Wq, *bq, *Wk, *bk, *Wv, *bv,
                *conv_w, *conv_b, *ln1_w, *ln1_b, *W1, *b1, *W2, *b2,
                *ln2_w, *ln2_b;
};

// ---------------------------------------------------------------------------
// primitives
// ---------------------------------------------------------------------------
__device__ __forceinline__ void mma16(float* c, const uint32_t* a, const uint32_t* b) {
    asm volatile(
        "mma.sync.aligned.m16n8k16.row.col.f32.f16.f16.f32 "
        "{%0,%1,%2,%3}, {%4,%5,%6,%7}, {%8,%9}, {%0,%1,%2,%3};\n"
        : "+f"(c[0]), "+f"(c[1]), "+f"(c[2]), "+f"(c[3])
        : "r"(a[0]), "r"(a[1]), "r"(a[2]), "r"(a[3]), "r"(b[0]), "r"(b[1]));
}
__device__ __forceinline__ void ldsm4(uint32_t* r, uint32_t addr) {
    asm volatile("ldmatrix.sync.aligned.m8n8.x4.shared.b16 {%0,%1,%2,%3}, [%4];"
                 : "=r"(r[0]), "=r"(r[1]), "=r"(r[2]), "=r"(r[3]) : "r"(addr));
}
__device__ __forceinline__ void cpa(void* dst, const void* src) {
    unsigned d = (unsigned)__cvta_generic_to_shared(dst);
    asm volatile("cp.async.cg.shared.global [%0], [%1], 16;\n" :: "r"(d), "l"(src));
}
#define CP_COMMIT() asm volatile("cp.async.commit_group;\n")
template<int N> __device__ __forceinline__ void waitg() {
    asm volatile("cp.async.wait_group %0;\n" :: "n"(N));
}
__device__ __forceinline__ float wsum(float v) {
    #pragma unroll
    for (int o = 16; o; o >>= 1) v += __shfl_xor_sync(0xffffffffu, v, o);
    return v;
}
__device__ __forceinline__ float wmax(float v) {
    #pragma unroll
    for (int o = 16; o; o >>= 1) v = fmaxf(v, __shfl_xor_sync(0xffffffffu, v, o));
    return v;
}
__device__ __forceinline__ float dot4(float4 a, float4 b) {
    return fmaf(a.x, b.x, fmaf(a.y, b.y, fmaf(a.z, b.z, a.w * b.w)));
}

// ---------------------------------------------------------------------------
// Stage 128x64h A-tile and B-tile: row = 128B, chunk u(0..7), phys = u^(r&7)
// ---------------------------------------------------------------------------
__device__ __forceinline__ void load_tile_h(char* stage,
                                            const __half* __restrict__ A,
                                            const __half* __restrict__ Bw,
                                            int K, int k0, int tid) {
    const int u = tid & 7, r0 = tid >> 3;            // r0: 0..31
    char* As = stage;
    char* Bs = stage + TILE_BYTES;
    #pragma unroll
    for (int i = 0; i < 4; ++i) {
        const int r  = i * 32 + r0;
        const int ph = r * 128 + 16 * (u ^ (r & 7));
        cpa(As + ph, A  + (size_t)r * K + k0 + 8 * u);
        cpa(Bs + ph, Bw + (size_t)r * K + k0 + 8 * u);
    }
}

// ---------------------------------------------------------------------------
// fp16 GEMM: out[m0:+128, nbase:+128] = inp @ wgt^T  (both half, K-major)
// EPI: 0 = raw fp32 store, 1 = +bias, exact GELU, half store
// ---------------------------------------------------------------------------
template<int KDIM, int EPI>
__global__ __launch_bounds__(256, 2) void k_gemm_h(
    const __half* __restrict__ inp, const __half* __restrict__ wgt,
    const float* __restrict__ bias, void* __restrict__ outv, int Nout)
{
    extern __shared__ char sm[];
    const uint32_t smb = (uint32_t)__cvta_generic_to_shared(sm);
    const int tid  = threadIdx.x;
    const int lane = tid & 31, w = tid >> 5;
    const int wm = w & 3, wn = w >> 2;
    const int gid = lane >> 2, tig = lane & 3;
    const int m0 = blockIdx.x * 128, nbase = blockIdx.y * 128;
    const __half* A  = inp + (size_t)m0 * KDIM;
    const __half* Bw = wgt + (size_t)nbase * KDIM;

    float acc[2][8][4];
    #pragma unroll
    for (int mt = 0; mt < 2; ++mt)
        #pragma unroll
        for (int j = 0; j < 8; ++j)
            #pragma unroll
            for (int e = 0; e < 4; ++e) acc[mt][j][e] = 0.f;

    // per-lane ldmatrix row geometry (offsets within a stage)
    const int arow0 = wm * 32 + (lane & 15);          // A rows for mt=0 (mt adds 16)
    const uint32_t aoffA0 = arow0 * 128;
    const uint32_t aoffA1 = (arow0 + 16) * 128;
    const int aswz0 = arow0 & 7, aswz1 = (arow0 + 16) & 7;
    const int achunk = lane >> 4;                     // +0 or +1 16B chunk

    const int q = lane >> 3;
    const int brow0 = wn * 64 + (q >> 1) * 8 + (lane & 7);  // jp adds 16
    const int bchunk = q & 1;

    constexpr int NT = KDIM / BK;
    load_tile_h(sm + 0 * STAGE_BYTES, A, Bw, KDIM, 0 * BK, tid); CP_COMMIT();
    load_tile_h(sm + 1 * STAGE_BYTES, A, Bw, KDIM, 1 * BK, tid); CP_COMMIT();

    int cs = 0, ls = 2;
    #pragma unroll 1
    for (int t = 0; t < NT; ++t) {
        if (t + 1 < NT) waitg<1>(); else waitg<0>();
        __syncthreads();
        const uint32_t Ast = smb + cs * STAGE_BYTES;
        const uint32_t Bst = Ast + TILE_BYTES;

        #pragma unroll
        for (int ks = 0; ks < 4; ++ks) {
            const int c0 = 2 * ks;                    // 16B-chunk base for this k16
            uint32_t a[2][4];
            ldsm4(a[0], Ast + aoffA0 + 16 * ((c0 + achunk) ^ aswz0));
            ldsm4(a[1], Ast + aoffA1 + 16 * ((c0 + achunk) ^ aswz1));
            uint32_t b[8][2];
            #pragma unroll
            for (int jp = 0; jp < 4; ++jp) {
                const int br = brow0 + jp * 16;
                uint32_t r4[4];
                ldsm4(r4, Bst + br * 128 + 16 * ((c0 + bchunk) ^ (br & 7)));
                b[2 * jp][0] = r4[0]; b[2 * jp][1] = r4[1];
                b[2 * jp + 1][0] = r4[2]; b[2 * jp + 1][1] = r4[3];
            }
            #pragma unroll
            for (int mt = 0; mt < 2; ++mt)
                #pragma unroll
                for (int j = 0; j < 8; ++j)
                    mma16(acc[mt][j], a[mt], b[j]);
        }
        if (t + 2 < NT) {
            load_tile_h(sm + ls * STAGE_BYTES, A, Bw, KDIM, (t + 2) * BK, tid);
            CP_COMMIT();
        }
        if (++cs == STAGES) cs = 0;
        if (++ls == STAGES) ls = 0;
    }

    // epilogue: row = m0 + wm*32 + mt*16 + half*8 + gid ; col = nbase + wn*64 + j*8 + 2*tig
    #pragma unroll
    for (int mt = 0; mt < 2; ++mt)
        #pragma unroll
        for (int half = 0; half < 2; ++half) {
            const int row = m0 + wm * 32 + mt * 16 + half * 8 + gid;
            #pragma unroll
            for (int j = 0; j < 8; ++j) {
                const int c = nbase + wn * 64 + j * 8 + 2 * tig;
                float v0 = acc[mt][j][half * 2 + 0];
                float v1 = acc[mt][j][half * 2 + 1];
                if (EPI == 1) {
                    v0 += bias[c]; v1 += bias[c + 1];
                    v0 = 0.5f * v0 * (1.0f + erff(v0 * 0.70710678118654752f));
                    v1 = 0.5f * v1 * (1.0f + erff(v1 * 0.70710678118654752f));
                    *(__half2*)((__half*)outv + (size_t)row * Nout + c) =
                        __floats2half2_rn(v0, v1);
                } else {
                    *(float2*)((float*)outv + (size_t)row * Nout + c) =
                        make_float2(v0, v1);
                }
            }
        }
}

// ---------------------------------------------------------------------------
// fused fp32->fp16 conversion: 4 segments (x, Wq, W1, W2) in one launch
// ---------------------------------------------------------------------------
#define N4_X   (MTOT * CCH / 4)
#define N4_WQ  (CCH * CCH / 4)
#define N4_W1  (2 * CCH * CCH / 4)
#define N4_W2  (2 * CCH * CCH / 4)
#define BL_X   (N4_X  / 256)     // 16384
#define BL_WQ  (N4_WQ / 256)     // 256
#define BL_W1  (N4_W1 / 256)     // 512
#define BL_W2  (N4_W2 / 256)     // 512
#define BL_TOT (BL_X + BL_WQ + BL_W1 + BL_W2)

__global__ void k_f2h_all(const float* __restrict__ x, const float* __restrict__ wq,
                          const float* __restrict__ w1, const float* __restrict__ w2,
                          __half* __restrict__ xh, __half* __restrict__ wqh,
                          __half* __restrict__ w1h, __half* __restrict__ w2h) {
    int b = blockIdx.x;
    const float* in; __half* out;
    if (b < BL_X)                 { in = x;  out = xh; }
    else if ((b -= BL_X) < BL_WQ) { in = wq; out = wqh; }
    else if ((b -= BL_WQ) < BL_W1){ in = w1; out = w1h; }
    else { b -= BL_W1;              in = w2; out = w2h; }
    const int i = b * 256 + threadIdx.x;
    const float4 v = ((const float4*)in)[i];
    ((__half2*)out)[2 * i]     = __floats2half2_rn(v.x, v.y);
    ((__half2*)out)[2 * i + 1] = __floats2half2_rn(v.z, v.w);
}

// ---------------------------------------------------------------------------
// Precompute: Pk[b,c] = pad[b]·Wk[c,:], Pv likewise; plus weight row-sums
// ---------------------------------------------------------------------------
__global__ void k_precompute(Params p) {
    __shared__ float padS[CONDC];
    const int bb = blockIdx.x;
    const int which = blockIdx.y;
    const float* W = which ? p.Wv : p.Wk;

    if (bb == BB) {
        for (int c = threadIdx.x; c < CCH; c += blockDim.x) {
            float s = 0.f;
            const float* wr = W + (size_t)c * CONDC;
            #pragma unroll 4
            for (int j = 0; j < CONDC; ++j) s += wr[j];
            (which ? g_WvSum : g_WkSum)[c] = s;
        }
        return;
    }
    for (int j = threadIdx.x; j < CONDC; j += blockDim.x) {
        int src = (j + LLEN - 2) % LLEN;
        padS[j] = p.cond_emb[bb * LLEN + src];
    }
    __syncthreads();
    for (int c = threadIdx.x; c < CCH; c += blockDim.x) {
        float s = 0.f;
        const float* wr = W + (size_t)c * CONDC;
        #pragma unroll 4
        for (int j = 0; j < CONDC; ++j) s = fmaf(padS[j], wr[j], s);
        (which ? g_Pv : g_Pk)[bb * CCH + c] = s;
    }
}

// ---------------------------------------------------------------------------
// Warp-per-row, float4: q=g_q+bq -> rank-1 attention -> +LN1 -> g_query + g_qh
// lane owns float4s c4 = j*32 + lane (j<4): each load = 512B contiguous/warp
// ---------------------------------------------------------------------------
__global__ __launch_bounds__(256) void k_attn_ln1(Params p) {
    __shared__ float convW[SSEQ], convB[SSEQ];
    const int tid = threadIdx.x;
    if (tid < SSEQ) { convW[tid] = p.conv_w[tid]; convB[tid] = p.conv_b[tid]; }
    __syncthreads();

    const int lane = tid & 31, w = tid >> 5;
    const int row = blockIdx.x * 8 + w;
    const int b = row >> 10;
    const float4* qr4 = (const float4*)(g_q + (size_t)row * CCH);
    const float4* Pk4 = (const float4*)(g_Pk + b * CCH);
    const float4* Pv4 = (const float4*)(g_Pv + b * CCH);
    const float4* Wk4 = (const float4*)g_WkSum;
    const float4* Wv4 = (const float4*)g_WvSum;
    const float4* bq4 = (const float4*)p.bq;
    const float4* bk4 = (const float4*)p.bk;
    const float4* bv4 = (const float4*)p.bv;

    float4 qv[4];
    float u = 0.f, vv = 0.f, c0 = 0.f;
    #pragma unroll
    for (int j = 0; j < 4; ++j) {
        const int c4 = j * 32 + lane;
        float4 q4 = qr4[c4];
        const float4 bq = bq4[c4];
        q4.x += bq.x; q4.y += bq.y; q4.z += bq.z; q4.w += bq.w;
        qv[j] = q4;
        u  += dot4(q4, Pk4[c4]);
        vv += dot4(q4, Wk4[c4]);
        c0 += dot4(q4, bk4[c4]);
    }
    u = wsum(u); vv = wsum(vv); c0 = wsum(c0);

    const float scl = 0.04419417382415922f;   // 1/sqrt(512)
    float sc[4], mx = -3.4e38f;
    #pragma unroll
    for (int ss = 0; ss < 4; ++ss) {
        const int s = lane + 32 * ss;
        sc[ss] = scl * (convW[s] * u + convB[s] * vv + c0);
        mx = fmaxf(mx, sc[ss]);
    }
    mx = wmax(mx);
    float z = 0.f, a1 = 0.f, a2 = 0.f;
    #pragma unroll
    for (int ss = 0; ss < 4; ++ss) {
        const int s = lane + 32 * ss;
        const float e = expf(sc[ss] - mx);
        z += e; a1 = fmaf(e, convW[s], a1); a2 = fmaf(e, convB[s], a2);
    }
    z = wsum(z); a1 = wsum(a1); a2 = wsum(a2);
    const float w1 = a1 / z, w2 = a2 / z;

    float s1 = 0.f, s2 = 0.f;
    #pragma unroll
    for (int j = 0; j < 4; ++j) {
        const int c4 = j * 32 + lane;
        const float4 pv = Pv4[c4], wv = Wv4[c4], bv = bv4[c4];
        float4 y;
        y.x = qv[j].x + fmaf(w1, pv.x, fmaf(w2, wv.x, bv.x));
        y.y = qv[j].y + fmaf(w1, pv.y, fmaf(w2, wv.y, bv.y));
        y.z = qv[j].z + fmaf(w1, pv.z, fmaf(w2, wv.z, bv.z));
        y.w = qv[j].w + fmaf(w1, pv.w, fmaf(w2, wv.w, bv.w));
        qv[j] = y;
        s1 += y.x + y.y + y.z + y.w;
        s2 += y.x * y.x + y.y * y.y + y.z * y.z + y.w * y.w;
    }
    s1 = wsum(s1); s2 = wsum(s2);
    const float mu = s1 * (1.f / CCH);
    const float rs = rsqrtf(s2 * (1.f / CCH) - mu * mu + 1e-5f);

    float4* qo4 = (float4*)(g_query + (size_t)row * CCH);
    __half* qoh = g_qh + (size_t)row * CCH;
    const float4* lw4 = (const float4*)p.ln1_w;
    const float4* lb4 = (const float4*)p.ln1_b;
    #pragma unroll
    for (int j = 0; j < 4; ++j) {
        const int c4 = j * 32 + lane;
        const float4 lw = lw4[c4], lb = lb4[c4];
        float4 o;
        o.x = (qv[j].x - mu) * rs * lw.x + lb.x;
        o.y = (qv[j].y - mu) * rs * lw.y + lb.y;
        o.z = (qv[j].z - mu) * rs * lw.z + lb.z;
        o.w = (qv[j].w - mu) * rs * lw.w + lb.w;
        qo4[c4] = o;
        __half2 h0 = __floats2half2_rn(o.x, o.y);
        __half2 h1 = __floats2half2_rn(o.z, o.w);
        *(__half2*)(qoh + 4 * c4)     = h0;
        *(__half2*)(qoh + 4 * c4 + 2) = h1;
    }
}

// ---------------------------------------------------------------------------
// Warp-per-row, float4: out = LN2(z + b2 + query) + x   (z lives in g_q)
// ---------------------------------------------------------------------------
__global__ __launch_bounds__(256) void k_ln2(Params p, float* __restrict__ out) {
    const int tid = threadIdx.x;
    const int lane = tid & 31, w = tid >> 5;
    const int row = blockIdx.x * 8 + w;
    const float4* zr4 = (const float4*)(g_q     + (size_t)row * CCH);
    const float4* qr4 = (const float4*)(g_query + (size_t)row * CCH);
    const float4* xr4 = (const float4*)(p.x     + (size_t)row * CCH);
    const float4* b24 = (const float4*)p.b2;

    float4 yv[4];
    float s1 = 0.f, s2 = 0.f;
    #pragma unroll
    for (int j = 0; j < 4; ++j) {
        const int c4 = j * 32 + lane;
        const float4 z4 = zr4[c4], q4 = qr4[c4], b4 = b24[c4];
        float4 y;
        y.x = z4.x + b4.x + q4.x;
        y.y = z4.y + b4.y + q4.y;
        y.z = z4.z + b4.z + q4.z;
        y.w = z4.w + b4.w + q4.w;
        yv[j] = y;
        s1 += y.x + y.y + y.z + y.w;
        s2 += y.x * y.x + y.y * y.y + y.z * y.z + y.w * y.w;
    }
    s1 = wsum(s1); s2 = wsum(s2);
    const float mu = s1 * (1.f / CCH);
    const float rs = rsqrtf(s2 * (1.f / CCH) - mu * mu + 1e-5f);

    float4* o4 = (float4*)(out + (size_t)row * CCH);
    const float4* lw4 = (const float4*)p.ln2_w;
    const float4* lb4 = (const float4*)p.ln2_b;
    #pragma unroll
    for (int j = 0; j < 4; ++j) {
        const int c4 = j * 32 + lane;
        const float4 lw = lw4[c4], lb = lb4[c4], x4 = xr4[c4];
        float4 o;
        o.x = (yv[j].x - mu) * rs * lw.x + lb.x + x4.x;
        o.y = (yv[j].y - mu) * rs * lw.y + lb.y + x4.y;
        o.z = (yv[j].z - mu) * rs * lw.z + lb.z + x4.z;
        o.w = (yv[j].w - mu) * rs * lw.w + lb.w + x4.w;
        o4[c4] = o;
    }
}

// ---------------------------------------------------------------------------
extern "C" void kernel_launch(void* const* d_in, const int* in_sizes, int n_in,
                              void* d_out, int out_size) {
    Params p;
    p.x        = (const float*)d_in[0];
    p.cond_emb = (const float*)d_in[1];
    p.Wq       = (const float*)d_in[2];
    p.bq       = (const float*)d_in[3];
    p.Wk       = (const float*)d_in[4];
    p.bk       = (const float*)d_in[5];
    p.Wv       = (const float*)d_in[6];
    p.bv       = (const float*)d_in[7];
    p.conv_w   = (const float*)d_in[8];
    p.conv_b   = (const float*)d_in[9];
    p.ln1_w    = (const float*)d_in[10];
    p.ln1_b    = (const float*)d_in[11];
    p.W1       = (const float*)d_in[12];
    p.b1       = (const float*)d_in[13];
    p.W2       = (const float*)d_in[14];
    p.b2       = (const float*)d_in[15];
    p.ln2_w    = (const float*)d_in[16];
    p.ln2_b    = (const float*)d_in[17];
    float* out = (float*)d_out;

    static bool attr_done = false;
    if (!attr_done) {
        cudaFuncSetAttribute(k_gemm_h<512, 0>,  cudaFuncAttributeMaxDynamicSharedMemorySize, SMEM_BYTES);
        cudaFuncSetAttribute(k_gemm_h<512, 1>,  cudaFuncAttributeMaxDynamicSharedMemorySize, SMEM_BYTES);
        cudaFuncSetAttribute(k_gemm_h<1024, 0>, cudaFuncAttributeMaxDynamicSharedMemorySize, SMEM_BYTES);
        attr_done = true;
    }

    float *dq;
    __half *dxh, *dqh, *dhh, *dWqh, *dW1h, *dW2h;
    cudaGetSymbolAddress((void**)&dq,   g_q);
    cudaGetSymbolAddress((void**)&dxh,  g_xh);
    cudaGetSymbolAddress((void**)&dqh,  g_qh);
    cudaGetSymbolAddress((void**)&dhh,  g_hh);
    cudaGetSymbolAddress((void**)&dWqh, g_Wqh);
    cudaGetSymbolAddress((void**)&dW1h, g_W1h);
    cudaGetSymbolAddress((void**)&dW2h, g_W2h);

    k_precompute<<<dim3(BB + 1, 2), 256>>>(p);
    k_f2h_all<<<BL_TOT, 256>>>(p.x, p.Wq, p.W1, p.W2, dxh, dWqh, dW1h, dW2h);

    // q = x @ Wq^T (fp32 out; bias folded into attn kernel)
    k_gemm_h<512, 0><<<dim3(MTOT / 128, 4), 256, SMEM_BYTES>>>(dxh, dWqh, nullptr, dq, CCH);
    k_attn_ln1<<<MTOT / 8, 256>>>(p);
    // h = gelu(query @ W1^T + b1) (half out)
    k_gemm_h<512, 1><<<dim3(MTOT / 128, 8), 256, SMEM_BYTES>>>(dqh, dW1h, p.b1, dhh, 2 * CCH);
    // z = h @ W2^T (fp32 out; bias in ln2) -> reuse g_q
    k_gemm_h<1024, 0><<<dim3(MTOT / 128, 4), 256, SMEM_BYTES>>>(dhh, dW2h, nullptr, dq, CCH);
    k_ln2<<<MTOT / 8, 256>>>(p, out);
}